// round 15
// baseline (speedup 1.0000x reference)
#include <cuda_runtime.h>
#include <cuda_bf16.h>
#include <math.h>
#include <stdint.h>

#define BATCH 128
#define CELLS 1024
#define XROWS 1025            // cells + meta
#define GROWS 1026            // + MAgg row
#define FDIM  128
#define MTOT  (BATCH*GROWS)   // 131328

typedef unsigned long long u64;

__device__ __forceinline__ float elu1(float v){ return v > 0.f ? v : (expf(v) - 1.f); }
__device__ __forceinline__ uint32_t smem_u32(const void* p){
    uint32_t a; asm("{ .reg .u64 t; cvta.to.shared.u64 t, %1; cvt.u32.u64 %0, t; }" : "=r"(a) : "l"(p));
    return a;
}
#define CP16(dst, src) asm volatile("cp.async.cg.shared.global [%0], [%1], 16;" :: "r"(dst), "l"(src))
#define CP_COMMIT()    asm volatile("cp.async.commit_group;")
#define CP_WAIT(n)     asm volatile("cp.async.wait_group %0;" :: "n"(n) : "memory")

// ---------------- scratch ----------------
__device__ __nv_bfloat16 g_xb0[(size_t)BATCH*XROWS*FDIM];
__device__ __nv_bfloat16 g_xb1[(size_t)BATCH*XROWS*FDIM];
__device__ __nv_bfloat16 g_uv[(size_t)BATCH*GROWS*256];   // 0-127: u, 128-255: v
__device__ __nv_bfloat16 g_magg[BATCH*FDIM];
__device__ __nv_bfloat16 g_wt[3*256*128];   // [l][n'=256][k=128]
__device__ float g_state[BATCH*640];

// ---------------- weight prep: Wt[l][n'][k] ----------------
__global__ void prep_wt(const float* __restrict__ Ws, const float* __restrict__ Wn,
                        __nv_bfloat16* __restrict__ Wt){
    int idx = blockIdx.x * blockDim.x + threadIdx.x;
    int l = idx >> 15;
    int r = idx & 32767;
    int n = r >> 7;
    int k = r & 127;
    float v = (n < 128) ? Ws[l*16384 + k*128 + n] : Wn[l*16384 + k*128 + (n-128)];
    Wt[idx] = __float2bfloat16(v);
}

// ---------------- meta aggregation ----------------
__global__ void meta_agg(const __nv_bfloat16* __restrict__ X, const float* __restrict__ G,
                         int srcF32, __nv_bfloat16* __restrict__ MAgg){
    __shared__ float2 sm[16][64];
    int b = blockIdx.x, t = threadIdx.x;
    int f2 = t & 63, p = t >> 6;
    float2 s = make_float2(0.f, 0.f);
    int c0 = p * 64;
    if (srcF32) {
        const float2* gb = (const float2*)(G + (size_t)b * CELLS * FDIM);
        #pragma unroll 8
        for (int c = c0; c < c0 + 64; c++) {
            float2 v = gb[c*64 + f2];
            s.x += v.x; s.y += v.y;
        }
    } else {
        const __nv_bfloat162* xb = (const __nv_bfloat162*)(X + (size_t)b * XROWS * FDIM);
        #pragma unroll 8
        for (int c = c0; c < c0 + 64; c++) {
            float2 v = __bfloat1622float2(xb[c*64 + f2]);
            s.x += v.x; s.y += v.y;
        }
    }
    sm[p][f2] = s;
    __syncthreads();
    if (p == 0) {
        s = sm[0][f2];
        #pragma unroll
        for (int i = 1; i < 16; i++) { s.x += sm[i][f2].x; s.y += sm[i][f2].y; }
        ((__nv_bfloat162*)MAgg)[b*64 + f2] = __float22bfloat162_rn(s);
    }
}

// ---------------- dense GEMM: UV = A @ Wt^T (+bias on u-half), R13 config ----------------
#define STR2 272
#define SMB2_OFF (128*STR2)
#define GEMM_SMEM (256*STR2)   // 69632

__device__ __forceinline__ void ldmA(uint32_t addr, uint32_t* r){
    asm volatile("ldmatrix.sync.aligned.m8n8.x4.shared.b16 {%0,%1,%2,%3}, [%4];"
        : "=r"(r[0]), "=r"(r[1]), "=r"(r[2]), "=r"(r[3]) : "r"(addr));
}

__global__ void __launch_bounds__(512, 2) gnn_gemm(
    const __nv_bfloat16* __restrict__ X, const float* __restrict__ G, int srcF32,
    const __nv_bfloat16* __restrict__ MAgg,
    const __nv_bfloat16* __restrict__ Wt, const float* __restrict__ bias,
    __nv_bfloat16* __restrict__ UV)
{
    extern __shared__ char smem[];
    uint32_t sb = smem_u32(smem);
    int t = threadIdx.x;
    int wid = t >> 5, lane = t & 31;
    int m0cta = blockIdx.x * 128;
    int nhalf = blockIdx.y;

    int rown = t >> 2;          // 0..127
    int part = t & 3;           // 32B sub-slice within a 128B k-half
    int row  = m0cta + rown;
    int b    = row / GROWS;
    int node = row - b * GROWS;

    const char* bsrc = (const char*)(Wt + ((size_t)(nhalf*128 + rown))*128);
    uint32_t bdst = sb + SMB2_OFF + rown*STR2;
    uint32_t adst = sb + rown*STR2;

    // ---- two cp.async stages over K halves ----
    #pragma unroll
    for (int s = 0; s < 2; s++) {
        int kb = s*128 + part*32;
        CP16(bdst + kb,      bsrc + kb);
        CP16(bdst + kb + 16, bsrc + kb + 16);
        if (node == GROWS - 1) {
            const uint4* src = (const uint4*)((const char*)(MAgg + b*FDIM) + kb);
            *(uint4*)(smem + rown*STR2 + kb)      = src[0];
            *(uint4*)(smem + rown*STR2 + kb + 16) = src[1];
        } else if (!srcF32) {
            const char* src = (const char*)(X + ((size_t)b * XROWS + node) * FDIM) + kb;
            CP16(adst + kb,      src);
            CP16(adst + kb + 16, src + 16);
        } else {
            if (node < CELLS) {
                const float* src = G + ((size_t)b * CELLS + node) * FDIM + (kb >> 1);
                #pragma unroll
                for (int j = 0; j < 2; j++) {
                    float4 v0 = *(const float4*)(src + j*8);
                    float4 v1 = *(const float4*)(src + j*8 + 4);
                    uint4 o;
                    __nv_bfloat162* ho = (__nv_bfloat162*)&o;
                    ho[0] = __float22bfloat162_rn(make_float2(v0.x, v0.y));
                    ho[1] = __float22bfloat162_rn(make_float2(v0.z, v0.w));
                    ho[2] = __float22bfloat162_rn(make_float2(v1.x, v1.y));
                    ho[3] = __float22bfloat162_rn(make_float2(v1.z, v1.w));
                    *(uint4*)(smem + rown*STR2 + kb + j*16) = o;
                }
            } else {
                uint4 z = make_uint4(0,0,0,0);
                *(uint4*)(smem + rown*STR2 + kb)      = z;
                *(uint4*)(smem + rown*STR2 + kb + 16) = z;
            }
        }
        CP_COMMIT();
    }

    int warp_m = wid >> 2;
    int warp_n = wid & 3;
    uint32_t saA = sb + (warp_m*32 + (lane & 15))*STR2 + (lane >> 4)*16;
    uint32_t saB = sb + SMB2_OFF + (warp_n*32 + (lane >> 4)*8 + (lane & 7))*STR2 + ((lane >> 3) & 1)*16;

    float acc[2][4][4];
    #pragma unroll
    for (int i = 0; i < 2; i++)
        #pragma unroll
        for (int j = 0; j < 4; j++)
            #pragma unroll
            for (int q = 0; q < 4; q++) acc[i][j][q] = 0.f;

    CP_WAIT(1);
    __syncthreads();

    #pragma unroll
    for (int stage = 0; stage < 2; stage++) {
        if (stage == 1) {
            CP_WAIT(0);
            __syncthreads();
        }
        #pragma unroll
        for (int ki = 0; ki < 4; ki++) {
            uint32_t ko = (stage*4 + ki) * 32;
            uint32_t a0[4], a1[4], b0[4], b1[4];
            ldmA(saA + ko, a0);
            ldmA(saA + 16*STR2 + ko, a1);
            ldmA(saB + ko, b0);
            ldmA(saB + 16*STR2 + ko, b1);
            uint32_t* afr[2] = { a0, a1 };
            uint32_t* bfr[2] = { b0, b1 };
            #pragma unroll
            for (int mf = 0; mf < 2; mf++)
                #pragma unroll
                for (int nf = 0; nf < 4; nf++) {
                    uint32_t rb0 = bfr[nf >> 1][(nf & 1)*2];
                    uint32_t rb1 = bfr[nf >> 1][(nf & 1)*2 + 1];
                    asm volatile("mma.sync.aligned.m16n8k16.row.col.f32.bf16.bf16.f32 "
                        "{%0,%1,%2,%3}, {%4,%5,%6,%7}, {%8,%9}, {%0,%1,%2,%3};"
                        : "+f"(acc[mf][nf][0]), "+f"(acc[mf][nf][1]),
                          "+f"(acc[mf][nf][2]), "+f"(acc[mf][nf][3])
                        : "r"(afr[mf][0]), "r"(afr[mf][1]), "r"(afr[mf][2]), "r"(afr[mf][3]),
                          "r"(rb0), "r"(rb1));
                }
        }
    }

    int gr = lane >> 2, gc = lane & 3;
    #pragma unroll
    for (int nf = 0; nf < 4; nf++) {
        int coln = warp_n*32 + nf*8 + 2*gc;
        float2 bb = make_float2(0.f, 0.f);
        if (nhalf == 0) bb = *(const float2*)(bias + coln);
        int colg = nhalf*128 + coln;
        #pragma unroll
        for (int mf = 0; mf < 2; mf++) {
            size_t r0 = (size_t)m0cta + warp_m*32 + mf*16 + gr;
            float v0 = acc[mf][nf][0] + bb.x;
            float v1 = acc[mf][nf][1] + bb.y;
            float v2 = acc[mf][nf][2] + bb.x;
            float v3 = acc[mf][nf][3] + bb.y;
            *(__nv_bfloat162*)(UV + r0 * 256 + colg)       = __float22bfloat162_rn(make_float2(v0, v1));
            *(__nv_bfloat162*)(UV + (r0 + 8) * 256 + colg) = __float22bfloat162_rn(make_float2(v2, v3));
        }
    }
}

// ---------------- stencil: y = elu(u + v[meta] + sum v[nbrs]), bf16 adds ----------------
__device__ __forceinline__ void badd8(const __nv_bfloat16* p, __nv_bfloat162* s){
    uint4 v = *(const uint4*)p;
    __nv_bfloat162* h = (__nv_bfloat162*)&v;
    #pragma unroll
    for (int i = 0; i < 4; i++) s[i] = __hadd2(s[i], h[i]);
}

__global__ void gnn_stencil(const __nv_bfloat16* __restrict__ UV, __nv_bfloat16* __restrict__ Y){
    int idx = blockIdx.x * blockDim.x + threadIdx.x;   // BATCH*XROWS*16
    int q = idx & 15;
    int nb = idx >> 4;
    int node = nb % XROWS;
    int b = nb / XROWS;
    const __nv_bfloat16* uvb = UV + (size_t)b * GROWS * 256;
    int qo = q * 8;

    __nv_bfloat162 s[4];
    {
        uint4 v = *(const uint4*)(uvb + (size_t)node*256 + qo);
        __nv_bfloat162* h = (__nv_bfloat162*)&v;
        #pragma unroll
        for (int i = 0; i < 4; i++) s[i] = h[i];
    }
    const __nv_bfloat16* vb = uvb + 128 + qo;
    if (node < CELLS) {
        badd8(vb + (size_t)CELLS*256, s);
        int r = node >> 5, c = node & 31;
        if (r > 0)  badd8(vb + (size_t)(node-32)*256, s);
        if (r < 31) badd8(vb + (size_t)(node+32)*256, s);
        if (c > 0)  badd8(vb + (size_t)(node-1)*256, s);
        if (c < 31) badd8(vb + (size_t)(node+1)*256, s);
    } else {
        badd8(vb + (size_t)(CELLS+1)*256, s);
    }
    uint4 o;
    __nv_bfloat162* ho = (__nv_bfloat162*)&o;
    #pragma unroll
    for (int i = 0; i < 4; i++) {
        float2 f = __bfloat1622float2(s[i]);
        ho[i] = __float22bfloat162_rn(make_float2(elu1(f.x), elu1(f.y)));
    }
    *(uint4*)(Y + ((size_t)b * XROWS + node) * FDIM + qo) = o;
}

// ---------------- gather 5 cells ----------------
__global__ void gather_state(const __nv_bfloat16* __restrict__ X, const int* __restrict__ pos,
                             float* __restrict__ state)
{
    int b = blockIdx.x;
    int f = threadIdx.x;
    int r = pos[2*b + 0];
    int c = pos[2*b + 1];
    const int dr[5] = {-1, 0, 1, 0, 0};
    const int dc[5] = { 0,-1, 0, 1, 0};
    #pragma unroll
    for (int o = 0; o < 5; o++) {
        int j  = (r + dr[o] + 1) * 32 + (c + dc[o] + 1);
        int jr = j / 34, jc = j % 34;
        float v = 0.f;
        if (jr >= 1 && jr <= 32 && jc >= 1 && jc <= 32) {
            int cell = (jr - 1) * 32 + (jc - 1);
            v = __bfloat162float(X[((size_t)b * XROWS + cell) * FDIM + f]);
        }
        state[b * 640 + o * FDIM + f] = v;
    }
}

// ---------------- fused MLP head: 32 CTAs x 4 rows, all layers + logits ----------------
__device__ __forceinline__ void f4fma(float4& a, float s, float4 w){
    a.x = fmaf(s, w.x, a.x); a.y = fmaf(s, w.y, a.y);
    a.z = fmaf(s, w.z, a.z); a.w = fmaf(s, w.w, a.w);
}

// N=512 layer: out has 512 floats; thread tl handles n = tl*4 (+0..3) and 256+tl*4
__device__ __forceinline__ void head_l512(const float* in, int K, const float* W,
                                          const float* bias, float* outp, int tl){
    float4 a0 = make_float4(0,0,0,0), a1 = make_float4(0,0,0,0);
    const float4* w = (const float4*)W;
    #pragma unroll 4
    for (int k = 0; k < K; k++) {
        float a = in[k];
        f4fma(a0, a, w[(size_t)k*128 + tl]);
        f4fma(a1, a, w[(size_t)k*128 + 64 + tl]);
    }
    float4 bb0 = ((const float4*)bias)[tl];
    float4 bb1 = ((const float4*)bias)[64 + tl];
    float4 o0, o1;
    o0.x = elu1(a0.x + bb0.x); o0.y = elu1(a0.y + bb0.y);
    o0.z = elu1(a0.z + bb0.z); o0.w = elu1(a0.w + bb0.w);
    o1.x = elu1(a1.x + bb1.x); o1.y = elu1(a1.y + bb1.y);
    o1.z = elu1(a1.z + bb1.z); o1.w = elu1(a1.w + bb1.w);
    *(float4*)(outp + tl*4)       = o0;
    *(float4*)(outp + 256 + tl*4) = o1;
}

// N=256 layer: thread tl handles n = tl*4 (+0..3)
__device__ __forceinline__ void head_l256(const float* in, int K, const float* W,
                                          const float* bias, float* outp, int tl){
    float4 a0 = make_float4(0,0,0,0);
    const float4* w = (const float4*)W;
    #pragma unroll 4
    for (int k = 0; k < K; k++) {
        float a = in[k];
        f4fma(a0, a, w[(size_t)k*64 + tl]);
    }
    float4 bb = ((const float4*)bias)[tl];
    float4 o;
    o.x = elu1(a0.x + bb.x); o.y = elu1(a0.y + bb.y);
    o.z = elu1(a0.z + bb.z); o.w = elu1(a0.w + bb.w);
    *(float4*)(outp + tl*4) = o;
}

__global__ void __launch_bounds__(256) fused_head(
    const float* __restrict__ st,
    const float* __restrict__ W1, const float* __restrict__ b1,
    const float* __restrict__ W2, const float* __restrict__ b2,
    const float* __restrict__ W3, const float* __restrict__ b3,
    const float* __restrict__ W4, const float* __restrict__ b4,
    const float* __restrict__ W5, const float* __restrict__ b5,
    const float* __restrict__ W6, const float* __restrict__ b6,
    const int* __restrict__ mask, float* __restrict__ out)
{
    __shared__ float sA[4][640];
    __shared__ float sB[4][512];
    int t = threadIdx.x;
    int r4 = t >> 6;      // row within CTA (0-3)
    int tl = t & 63;      // lane within row group
    int b = blockIdx.x * 4 + r4;

    // load state
    #pragma unroll
    for (int i = tl; i < 640; i += 64) sA[r4][i] = st[b*640 + i];
    __syncthreads();

    head_l512(sA[r4], 640, W1, b1, sB[r4], tl);   // 640 -> 512
    __syncthreads();
    head_l512(sB[r4], 512, W2, b2, sA[r4], tl);   // 512 -> 512
    __syncthreads();
    head_l256(sA[r4], 512, W3, b3, sB[r4], tl);   // 512 -> 256
    __syncthreads();
    head_l256(sB[r4], 256, W4, b4, sA[r4], tl);   // 256 -> 256
    __syncthreads();
    head_l256(sA[r4], 256, W5, b5, sB[r4], tl);   // 256 -> 256
    __syncthreads();

    // logits: 256 -> 19 + mask
    if (tl < 19) {
        float s = b6[tl];
        const float* p = sB[r4];
        #pragma unroll 8
        for (int k = 0; k < 256; k++) s += p[k] * W6[k*19 + tl];
        int m = mask[b*19 + tl];
        out[b*19 + tl] = s + (m > 0 ? 0.f : -3.4028234663852886e38f);
    }
}

// ---------------- launch ----------------
extern "C" void kernel_launch(void* const* d_in, const int* in_sizes, int n_in,
                              void* d_out, int out_size)
{
    const float* gmap  = (const float*)d_in[0];
    const int*   pos   = (const int*)  d_in[1];
    const int*   amask = (const int*)  d_in[2];
    const float* Ws    = (const float*)d_in[3];
    const float* Wn    = (const float*)d_in[4];
    const float* bs    = (const float*)d_in[5];
    const float* W_d1  = (const float*)d_in[6];
    const float* b_d1  = (const float*)d_in[7];
    const float* W_d2  = (const float*)d_in[8];
    const float* b_d2  = (const float*)d_in[9];
    const float* W_d3  = (const float*)d_in[10];
    const float* b_d3  = (const float*)d_in[11];
    const float* W_p1  = (const float*)d_in[12];
    const float* b_p1  = (const float*)d_in[13];
    const float* W_p2  = (const float*)d_in[14];
    const float* b_p2  = (const float*)d_in[15];
    const float* W_p3  = (const float*)d_in[16];
    const float* b_p3  = (const float*)d_in[17];
    float* out = (float*)d_out;

    __nv_bfloat16 *x0, *x1, *uv, *ma, *wt;
    float *st;
    cudaGetSymbolAddress((void**)&x0, g_xb0);
    cudaGetSymbolAddress((void**)&x1, g_xb1);
    cudaGetSymbolAddress((void**)&uv, g_uv);
    cudaGetSymbolAddress((void**)&ma, g_magg);
    cudaGetSymbolAddress((void**)&wt, g_wt);
    cudaGetSymbolAddress((void**)&st, g_state);

    cudaFuncSetAttribute(gnn_gemm, cudaFuncAttributeMaxDynamicSharedMemorySize, GEMM_SMEM);

    prep_wt<<<(3*256*128)/256, 256>>>(Ws, Wn, wt);

    dim3 gg(MTOT/128, 2);
    // layer 0 (A from gmap fp32)
    meta_agg<<<BATCH, 1024>>>(nullptr, gmap, 1, ma);
    gnn_gemm<<<gg, 512, GEMM_SMEM>>>(nullptr, gmap, 1, ma, wt, bs, uv);
    gnn_stencil<<<(BATCH*XROWS*16)/256, 256>>>(uv, x0);
    // layer 1
    meta_agg<<<BATCH, 1024>>>(x0, nullptr, 0, ma);
    gnn_gemm<<<gg, 512, GEMM_SMEM>>>(x0, nullptr, 0, ma, wt + 256*128, bs + 128, uv);
    gnn_stencil<<<(BATCH*XROWS*16)/256, 256>>>(uv, x1);
    // layer 2
    meta_agg<<<BATCH, 1024>>>(x1, nullptr, 0, ma);
    gnn_gemm<<<gg, 512, GEMM_SMEM>>>(x1, nullptr, 0, ma, wt + 2*256*128, bs + 256, uv);
    gnn_stencil<<<(BATCH*XROWS*16)/256, 256>>>(uv, x0);

    gather_state<<<BATCH, 128>>>(x0, pos, st);

    fused_head<<<BATCH/4, 256>>>(st, W_d1, b_d1, W_d2, b_d2, W_d3, b_d3,
                                 W_p1, b_p1, W_p2, b_p2, W_p3, b_p3, amask, out);
}

// round 16
// speedup vs baseline: 1.8944x; 1.8944x over previous
#include <cuda_runtime.h>
#include <cuda_bf16.h>
#include <math.h>
#include <stdint.h>

#define BATCH 128
#define CELLS 1024
#define XROWS 1025            // cells + meta
#define GROWS 1026            // + MAgg row
#define FDIM  128
#define MTOT  (BATCH*GROWS)   // 131328

typedef unsigned long long u64;
union F2 { u64 u; float2 f; };

__device__ __forceinline__ u64 pack2(float lo, float hi){
    u64 r; asm("mov.b64 %0, {%1, %2};" : "=l"(r) : "f"(lo), "f"(hi)); return r;
}
__device__ __forceinline__ void ffma2(u64& d, u64 a, u64 b){
    asm("fma.rn.f32x2 %0, %1, %2, %0;" : "+l"(d) : "l"(a), "l"(b));
}
__device__ __forceinline__ float elu1(float v){ return v > 0.f ? v : (expf(v) - 1.f); }
__device__ __forceinline__ uint32_t smem_u32(const void* p){
    uint32_t a; asm("{ .reg .u64 t; cvta.to.shared.u64 t, %1; cvt.u32.u64 %0, t; }" : "=r"(a) : "l"(p));
    return a;
}
#define CP16(dst, src) asm volatile("cp.async.cg.shared.global [%0], [%1], 16;" :: "r"(dst), "l"(src))
#define CP_COMMIT()    asm volatile("cp.async.commit_group;")
#define CP_WAIT(n)     asm volatile("cp.async.wait_group %0;" :: "n"(n) : "memory")

// ---------------- scratch ----------------
__device__ __nv_bfloat16 g_xb0[(size_t)BATCH*XROWS*FDIM];
__device__ __nv_bfloat16 g_xb1[(size_t)BATCH*XROWS*FDIM];
__device__ __nv_bfloat16 g_uv[(size_t)BATCH*GROWS*256];   // 0-127: u, 128-255: v
__device__ __nv_bfloat16 g_magg[BATCH*FDIM];
__device__ __nv_bfloat16 g_wt[3*256*128];   // [l][n'=256][k=128]
__device__ float g_state[BATCH*640];
__device__ float g_h1[BATCH*512];
__device__ float g_h2[BATCH*512];
__device__ float g_ft[BATCH*256];
__device__ float g_p1[BATCH*256];
__device__ float g_p2[BATCH*256];

// ---------------- weight prep: Wt[l][n'][k] ----------------
__global__ void prep_wt(const float* __restrict__ Ws, const float* __restrict__ Wn,
                        __nv_bfloat16* __restrict__ Wt){
    int idx = blockIdx.x * blockDim.x + threadIdx.x;
    int l = idx >> 15;
    int r = idx & 32767;
    int n = r >> 7;
    int k = r & 127;
    float v = (n < 128) ? Ws[l*16384 + k*128 + n] : Wn[l*16384 + k*128 + (n-128)];
    Wt[idx] = __float2bfloat16(v);
}

// ---------------- meta aggregation ----------------
__global__ void meta_agg(const __nv_bfloat16* __restrict__ X, const float* __restrict__ G,
                         int srcF32, __nv_bfloat16* __restrict__ MAgg){
    __shared__ float2 sm[16][64];
    int b = blockIdx.x, t = threadIdx.x;
    int f2 = t & 63, p = t >> 6;
    float2 s = make_float2(0.f, 0.f);
    int c0 = p * 64;
    if (srcF32) {
        const float2* gb = (const float2*)(G + (size_t)b * CELLS * FDIM);
        #pragma unroll 8
        for (int c = c0; c < c0 + 64; c++) {
            float2 v = gb[c*64 + f2];
            s.x += v.x; s.y += v.y;
        }
    } else {
        const __nv_bfloat162* xb = (const __nv_bfloat162*)(X + (size_t)b * XROWS * FDIM);
        #pragma unroll 8
        for (int c = c0; c < c0 + 64; c++) {
            float2 v = __bfloat1622float2(xb[c*64 + f2]);
            s.x += v.x; s.y += v.y;
        }
    }
    sm[p][f2] = s;
    __syncthreads();
    if (p == 0) {
        s = sm[0][f2];
        #pragma unroll
        for (int i = 1; i < 16; i++) { s.x += sm[i][f2].x; s.y += sm[i][f2].y; }
        ((__nv_bfloat162*)MAgg)[b*64 + f2] = __float22bfloat162_rn(s);
    }
}

// ---------------- dense GEMM: UV = A @ Wt^T (+bias on u-half) ----------------
// CTA tile 128x128, K=128 split into 2 cp.async stages (overlap fill/MMA).
// 512 threads = 16 warps (4m x 4n), warp 32x32. grid (1026, 2). 2 CTAs/SM.
#define STR2 272
#define SMB2_OFF (128*STR2)
#define GEMM_SMEM (256*STR2)   // 69632

__device__ __forceinline__ void ldmA(uint32_t addr, uint32_t* r){
    asm volatile("ldmatrix.sync.aligned.m8n8.x4.shared.b16 {%0,%1,%2,%3}, [%4];"
        : "=r"(r[0]), "=r"(r[1]), "=r"(r[2]), "=r"(r[3]) : "r"(addr));
}

__global__ void __launch_bounds__(512, 2) gnn_gemm(
    const __nv_bfloat16* __restrict__ X, const float* __restrict__ G, int srcF32,
    const __nv_bfloat16* __restrict__ MAgg,
    const __nv_bfloat16* __restrict__ Wt, const float* __restrict__ bias,
    __nv_bfloat16* __restrict__ UV)
{
    extern __shared__ char smem[];
    uint32_t sb = smem_u32(smem);
    int t = threadIdx.x;
    int wid = t >> 5, lane = t & 31;
    int m0cta = blockIdx.x * 128;
    int nhalf = blockIdx.y;

    int rown = t >> 2;          // 0..127
    int part = t & 3;           // 32B sub-slice within a 128B k-half
    int row  = m0cta + rown;
    int b    = row / GROWS;
    int node = row - b * GROWS;

    const char* bsrc = (const char*)(Wt + ((size_t)(nhalf*128 + rown))*128);
    uint32_t bdst = sb + SMB2_OFF + rown*STR2;
    uint32_t adst = sb + rown*STR2;

    // ---- two cp.async stages over K halves ----
    #pragma unroll
    for (int s = 0; s < 2; s++) {
        int kb = s*128 + part*32;
        CP16(bdst + kb,      bsrc + kb);
        CP16(bdst + kb + 16, bsrc + kb + 16);
        if (node == GROWS - 1) {
            const uint4* src = (const uint4*)((const char*)(MAgg + b*FDIM) + kb);
            *(uint4*)(smem + rown*STR2 + kb)      = src[0];
            *(uint4*)(smem + rown*STR2 + kb + 16) = src[1];
        } else if (!srcF32) {
            const char* src = (const char*)(X + ((size_t)b * XROWS + node) * FDIM) + kb;
            CP16(adst + kb,      src);
            CP16(adst + kb + 16, src + 16);
        } else {
            if (node < CELLS) {
                const float* src = G + ((size_t)b * CELLS + node) * FDIM + (kb >> 1);
                #pragma unroll
                for (int j = 0; j < 2; j++) {
                    float4 v0 = *(const float4*)(src + j*8);
                    float4 v1 = *(const float4*)(src + j*8 + 4);
                    uint4 o;
                    __nv_bfloat162* ho = (__nv_bfloat162*)&o;
                    ho[0] = __float22bfloat162_rn(make_float2(v0.x, v0.y));
                    ho[1] = __float22bfloat162_rn(make_float2(v0.z, v0.w));
                    ho[2] = __float22bfloat162_rn(make_float2(v1.x, v1.y));
                    ho[3] = __float22bfloat162_rn(make_float2(v1.z, v1.w));
                    *(uint4*)(smem + rown*STR2 + kb + j*16) = o;
                }
            } else {
                uint4 z = make_uint4(0,0,0,0);
                *(uint4*)(smem + rown*STR2 + kb)      = z;
                *(uint4*)(smem + rown*STR2 + kb + 16) = z;
            }
        }
        CP_COMMIT();
    }

    int warp_m = wid >> 2;
    int warp_n = wid & 3;
    uint32_t saA = sb + (warp_m*32 + (lane & 15))*STR2 + (lane >> 4)*16;
    uint32_t saB = sb + SMB2_OFF + (warp_n*32 + (lane >> 4)*8 + (lane & 7))*STR2 + ((lane >> 3) & 1)*16;

    float acc[2][4][4];
    #pragma unroll
    for (int i = 0; i < 2; i++)
        #pragma unroll
        for (int j = 0; j < 4; j++)
            #pragma unroll
            for (int q = 0; q < 4; q++) acc[i][j][q] = 0.f;

    CP_WAIT(1);
    __syncthreads();

    #pragma unroll
    for (int stage = 0; stage < 2; stage++) {
        if (stage == 1) {
            CP_WAIT(0);
            __syncthreads();
        }
        #pragma unroll
        for (int ki = 0; ki < 4; ki++) {
            uint32_t ko = (stage*4 + ki) * 32;
            uint32_t a0[4], a1[4], b0[4], b1[4];
            ldmA(saA + ko, a0);
            ldmA(saA + 16*STR2 + ko, a1);
            ldmA(saB + ko, b0);
            ldmA(saB + 16*STR2 + ko, b1);
            uint32_t* afr[2] = { a0, a1 };
            uint32_t* bfr[2] = { b0, b1 };
            #pragma unroll
            for (int mf = 0; mf < 2; mf++)
                #pragma unroll
                for (int nf = 0; nf < 4; nf++) {
                    uint32_t rb0 = bfr[nf >> 1][(nf & 1)*2];
                    uint32_t rb1 = bfr[nf >> 1][(nf & 1)*2 + 1];
                    asm volatile("mma.sync.aligned.m16n8k16.row.col.f32.bf16.bf16.f32 "
                        "{%0,%1,%2,%3}, {%4,%5,%6,%7}, {%8,%9}, {%0,%1,%2,%3};"
                        : "+f"(acc[mf][nf][0]), "+f"(acc[mf][nf][1]),
                          "+f"(acc[mf][nf][2]), "+f"(acc[mf][nf][3])
                        : "r"(afr[mf][0]), "r"(afr[mf][1]), "r"(afr[mf][2]), "r"(afr[mf][3]),
                          "r"(rb0), "r"(rb1));
                }
        }
    }

    int gr = lane >> 2, gc = lane & 3;
    #pragma unroll
    for (int nf = 0; nf < 4; nf++) {
        int coln = warp_n*32 + nf*8 + 2*gc;
        float2 bb = make_float2(0.f, 0.f);
        if (nhalf == 0) bb = *(const float2*)(bias + coln);
        int colg = nhalf*128 + coln;
        #pragma unroll
        for (int mf = 0; mf < 2; mf++) {
            size_t r0 = (size_t)m0cta + warp_m*32 + mf*16 + gr;
            float v0 = acc[mf][nf][0] + bb.x;
            float v1 = acc[mf][nf][1] + bb.y;
            float v2 = acc[mf][nf][2] + bb.x;
            float v3 = acc[mf][nf][3] + bb.y;
            *(__nv_bfloat162*)(UV + r0 * 256 + colg)       = __float22bfloat162_rn(make_float2(v0, v1));
            *(__nv_bfloat162*)(UV + (r0 + 8) * 256 + colg) = __float22bfloat162_rn(make_float2(v2, v3));
        }
    }
}

// ---------------- stencil: y = elu(u + v[meta] + sum v[nbrs]), bf16 adds ----------------
__device__ __forceinline__ void badd8(const __nv_bfloat16* p, __nv_bfloat162* s){
    uint4 v = *(const uint4*)p;
    __nv_bfloat162* h = (__nv_bfloat162*)&v;
    #pragma unroll
    for (int i = 0; i < 4; i++) s[i] = __hadd2(s[i], h[i]);
}

__global__ void gnn_stencil(const __nv_bfloat16* __restrict__ UV, __nv_bfloat16* __restrict__ Y){
    int idx = blockIdx.x * blockDim.x + threadIdx.x;   // BATCH*XROWS*16
    int q = idx & 15;
    int nb = idx >> 4;
    int node = nb % XROWS;
    int b = nb / XROWS;
    const __nv_bfloat16* uvb = UV + (size_t)b * GROWS * 256;
    int qo = q * 8;

    __nv_bfloat162 s[4];
    {
        uint4 v = *(const uint4*)(uvb + (size_t)node*256 + qo);
        __nv_bfloat162* h = (__nv_bfloat162*)&v;
        #pragma unroll
        for (int i = 0; i < 4; i++) s[i] = h[i];
    }
    const __nv_bfloat16* vb = uvb + 128 + qo;
    if (node < CELLS) {
        badd8(vb + (size_t)CELLS*256, s);
        int r = node >> 5, c = node & 31;
        if (r > 0)  badd8(vb + (size_t)(node-32)*256, s);
        if (r < 31) badd8(vb + (size_t)(node+32)*256, s);
        if (c > 0)  badd8(vb + (size_t)(node-1)*256, s);
        if (c < 31) badd8(vb + (size_t)(node+1)*256, s);
    } else {
        badd8(vb + (size_t)(CELLS+1)*256, s);
    }
    uint4 o;
    __nv_bfloat162* ho = (__nv_bfloat162*)&o;
    #pragma unroll
    for (int i = 0; i < 4; i++) {
        float2 f = __bfloat1622float2(s[i]);
        ho[i] = __float22bfloat162_rn(make_float2(elu1(f.x), elu1(f.y)));
    }
    *(uint4*)(Y + ((size_t)b * XROWS + node) * FDIM + qo) = o;
}

// ---------------- gather 5 cells ----------------
__global__ void gather_state(const __nv_bfloat16* __restrict__ X, const int* __restrict__ pos,
                             float* __restrict__ state)
{
    int b = blockIdx.x;
    int f = threadIdx.x;
    int r = pos[2*b + 0];
    int c = pos[2*b + 1];
    const int dr[5] = {-1, 0, 1, 0, 0};
    const int dc[5] = { 0,-1, 0, 1, 0};
    #pragma unroll
    for (int o = 0; o < 5; o++) {
        int j  = (r + dr[o] + 1) * 32 + (c + dc[o] + 1);
        int jr = j / 34, jc = j % 34;
        float v = 0.f;
        if (jr >= 1 && jr <= 32 && jc >= 1 && jc <= 32) {
            int cell = (jr - 1) * 32 + (jc - 1);
            v = __bfloat162float(X[((size_t)b * XROWS + cell) * FDIM + f]);
        }
        state[b * 640 + o * FDIM + f] = v;
    }
}

// ---------------- small MLP GEMM (fp32, f32x2), tile 32x64 ----------------
template<bool ELU>
__global__ void __launch_bounds__(256) mlp_gemm(
    const float* __restrict__ A, const float* __restrict__ W,
    const float* __restrict__ bias, float* __restrict__ C, int K, int N)
{
    __shared__ float sAm[32][36];
    __shared__ float sWm[32][68];
    int t = threadIdx.x;
    int tx = t & 15;
    int ty = t >> 4;
    int m0 = blockIdx.y * 32;
    int n0 = blockIdx.x * 64;

    u64 acc[2][2];
    acc[0][0] = acc[0][1] = acc[1][0] = acc[1][1] = 0ULL;

    int arow = t >> 3, acg = t & 7;
    int wr = t >> 4, wn = (t & 15) * 4;

    for (int kk = 0; kk < K; kk += 32) {
        *(float4*)&sAm[arow][acg*4] = *(const float4*)(A + (size_t)(m0 + arow) * K + kk + acg*4);
        *(float4*)&sWm[wr][wn]      = *(const float4*)(W + (size_t)(kk + wr) * N + n0 + wn);
        *(float4*)&sWm[wr+16][wn]   = *(const float4*)(W + (size_t)(kk + wr + 16) * N + n0 + wn);
        __syncthreads();
        #pragma unroll
        for (int k = 0; k < 32; k++) {
            F2 b0, b1;
            b0.f = *(const float2*)&sWm[k][tx*4];
            b1.f = *(const float2*)&sWm[k][tx*4 + 2];
            #pragma unroll
            for (int i = 0; i < 2; i++) {
                float av = sAm[ty*2+i][k];
                u64 ap = pack2(av, av);
                ffma2(acc[i][0], ap, b0.u);
                ffma2(acc[i][1], ap, b1.u);
            }
        }
        __syncthreads();
    }

    float4 bb = *(const float4*)(bias + n0 + tx*4);
    #pragma unroll
    for (int i = 0; i < 2; i++) {
        F2 u0, u1; u0.u = acc[i][0]; u1.u = acc[i][1];
        float4 o;
        o.x = u0.f.x + bb.x; o.y = u0.f.y + bb.y;
        o.z = u1.f.x + bb.z; o.w = u1.f.y + bb.w;
        if (ELU) { o.x = elu1(o.x); o.y = elu1(o.y); o.z = elu1(o.z); o.w = elu1(o.w); }
        *(float4*)(C + (size_t)(m0 + ty*2 + i) * N + n0 + tx*4) = o;
    }
}

// ---------------- logits + mask ----------------
__global__ void logits_k(const float* __restrict__ P2, const float* __restrict__ W,
                         const float* __restrict__ bias, const int* __restrict__ mask,
                         float* __restrict__ out)
{
    int b = blockIdx.x;
    int a = threadIdx.x;
    if (a >= 19) return;
    float s = bias[a];
    const float* p = P2 + b * 256;
    #pragma unroll 8
    for (int k = 0; k < 256; k++) s += p[k] * W[k * 19 + a];
    int m = mask[b * 19 + a];
    out[b * 19 + a] = s + (m > 0 ? 0.f : -3.4028234663852886e38f);
}

// ---------------- launch ----------------
extern "C" void kernel_launch(void* const* d_in, const int* in_sizes, int n_in,
                              void* d_out, int out_size)
{
    const float* gmap  = (const float*)d_in[0];
    const int*   pos   = (const int*)  d_in[1];
    const int*   amask = (const int*)  d_in[2];
    const float* Ws    = (const float*)d_in[3];
    const float* Wn    = (const float*)d_in[4];
    const float* bs    = (const float*)d_in[5];
    const float* W_d1  = (const float*)d_in[6];
    const float* b_d1  = (const float*)d_in[7];
    const float* W_d2  = (const float*)d_in[8];
    const float* b_d2  = (const float*)d_in[9];
    const float* W_d3  = (const float*)d_in[10];
    const float* b_d3  = (const float*)d_in[11];
    const float* W_p1  = (const float*)d_in[12];
    const float* b_p1  = (const float*)d_in[13];
    const float* W_p2  = (const float*)d_in[14];
    const float* b_p2  = (const float*)d_in[15];
    const float* W_p3  = (const float*)d_in[16];
    const float* b_p3  = (const float*)d_in[17];
    float* out = (float*)d_out;

    __nv_bfloat16 *x0, *x1, *uv, *ma, *wt;
    float *st, *h1, *h2, *ft, *p1, *p2;
    cudaGetSymbolAddress((void**)&x0, g_xb0);
    cudaGetSymbolAddress((void**)&x1, g_xb1);
    cudaGetSymbolAddress((void**)&uv, g_uv);
    cudaGetSymbolAddress((void**)&ma, g_magg);
    cudaGetSymbolAddress((void**)&wt, g_wt);
    cudaGetSymbolAddress((void**)&st, g_state);
    cudaGetSymbolAddress((void**)&h1, g_h1);
    cudaGetSymbolAddress((void**)&h2, g_h2);
    cudaGetSymbolAddress((void**)&ft, g_ft);
    cudaGetSymbolAddress((void**)&p1, g_p1);
    cudaGetSymbolAddress((void**)&p2, g_p2);

    cudaFuncSetAttribute(gnn_gemm, cudaFuncAttributeMaxDynamicSharedMemorySize, GEMM_SMEM);

    prep_wt<<<(3*256*128)/256, 256>>>(Ws, Wn, wt);

    dim3 gg(MTOT/128, 2);
    // layer 0 (A from gmap fp32)
    meta_agg<<<BATCH, 1024>>>(nullptr, gmap, 1, ma);
    gnn_gemm<<<gg, 512, GEMM_SMEM>>>(nullptr, gmap, 1, ma, wt, bs, uv);
    gnn_stencil<<<(BATCH*XROWS*16)/256, 256>>>(uv, x0);
    // layer 1
    meta_agg<<<BATCH, 1024>>>(x0, nullptr, 0, ma);
    gnn_gemm<<<gg, 512, GEMM_SMEM>>>(x0, nullptr, 0, ma, wt + 256*128, bs + 128, uv);
    gnn_stencil<<<(BATCH*XROWS*16)/256, 256>>>(uv, x1);
    // layer 2
    meta_agg<<<BATCH, 1024>>>(x1, nullptr, 0, ma);
    gnn_gemm<<<gg, 512, GEMM_SMEM>>>(x1, nullptr, 0, ma, wt + 2*256*128, bs + 256, uv);
    gnn_stencil<<<(BATCH*XROWS*16)/256, 256>>>(uv, x0);

    gather_state<<<BATCH, 128>>>(x0, pos, st);

    mlp_gemm<true><<<dim3(8, 4), 256>>>(st, W_d1, b_d1, h1, 640, 512);
    mlp_gemm<true><<<dim3(8, 4), 256>>>(h1, W_d2, b_d2, h2, 512, 512);
    mlp_gemm<true><<<dim3(4, 4), 256>>>(h2, W_d3, b_d3, ft, 512, 256);
    mlp_gemm<true><<<dim3(4, 4), 256>>>(ft, W_p1, b_p1, p1, 256, 256);
    mlp_gemm<true><<<dim3(4, 4), 256>>>(p1, W_p2, b_p2, p2, 256, 256);

    logits_k<<<BATCH, 32>>>(p2, W_p3, b_p3, amask, out);
}

// round 17
// speedup vs baseline: 2.0661x; 1.0906x over previous
#include <cuda_runtime.h>
#include <cuda_bf16.h>
#include <math.h>
#include <stdint.h>

#define BATCH 128
#define CELLS 1024
#define XROWS 1025            // cells + meta
#define GROWS 1026            // + MAgg row
#define FDIM  128
#define MTOT  (BATCH*GROWS)   // 131328

typedef unsigned long long u64;
union F2 { u64 u; float2 f; };

__device__ __forceinline__ u64 pack2(float lo, float hi){
    u64 r; asm("mov.b64 %0, {%1, %2};" : "=l"(r) : "f"(lo), "f"(hi)); return r;
}
__device__ __forceinline__ void ffma2(u64& d, u64 a, u64 b){
    asm("fma.rn.f32x2 %0, %1, %2, %0;" : "+l"(d) : "l"(a), "l"(b));
}
__device__ __forceinline__ float elu1(float v){ return v > 0.f ? v : (expf(v) - 1.f); }
__device__ __forceinline__ uint32_t smem_u32(const void* p){
    uint32_t a; asm("{ .reg .u64 t; cvta.to.shared.u64 t, %1; cvt.u32.u64 %0, t; }" : "=r"(a) : "l"(p));
    return a;
}
#define CP16(dst, src) asm volatile("cp.async.cg.shared.global [%0], [%1], 16;" :: "r"(dst), "l"(src))
#define CP_COMMIT()    asm volatile("cp.async.commit_group;")
#define CP_WAIT(n)     asm volatile("cp.async.wait_group %0;" :: "n"(n) : "memory")

// ---------------- scratch ----------------
__device__ __nv_bfloat16 g_xb0[(size_t)BATCH*XROWS*FDIM];
__device__ __nv_bfloat16 g_xb1[(size_t)BATCH*XROWS*FDIM];
__device__ __nv_bfloat16 g_uv[(size_t)BATCH*GROWS*256];   // 0-127: u, 128-255: v
__device__ __nv_bfloat16 g_magg[BATCH*FDIM];
__device__ __nv_bfloat16 g_wt[3*256*128];   // [l][n'=256][k=128]
__device__ float g_state[BATCH*640];
__device__ float g_h1[BATCH*512];
__device__ float g_h2[BATCH*512];
__device__ float g_ft[BATCH*256];
__device__ float g_p1[BATCH*256];
__device__ float g_p2[BATCH*256];

// ---------------- weight prep: Wt[l][n'][k] ----------------
__global__ void prep_wt(const float* __restrict__ Ws, const float* __restrict__ Wn,
                        __nv_bfloat16* __restrict__ Wt){
    int idx = blockIdx.x * blockDim.x + threadIdx.x;
    int l = idx >> 15;
    int r = idx & 32767;
    int n = r >> 7;
    int k = r & 127;
    float v = (n < 128) ? Ws[l*16384 + k*128 + n] : Wn[l*16384 + k*128 + (n-128)];
    Wt[idx] = __float2bfloat16(v);
}

// ---------------- meta aggregation ----------------
__global__ void meta_agg(const __nv_bfloat16* __restrict__ X, const float* __restrict__ G,
                         int srcF32, __nv_bfloat16* __restrict__ MAgg){
    __shared__ float2 sm[16][64];
    int b = blockIdx.x, t = threadIdx.x;
    int f2 = t & 63, p = t >> 6;
    float2 s = make_float2(0.f, 0.f);
    int c0 = p * 64;
    if (srcF32) {
        const float2* gb = (const float2*)(G + (size_t)b * CELLS * FDIM);
        #pragma unroll 8
        for (int c = c0; c < c0 + 64; c++) {
            float2 v = gb[c*64 + f2];
            s.x += v.x; s.y += v.y;
        }
    } else {
        const __nv_bfloat162* xb = (const __nv_bfloat162*)(X + (size_t)b * XROWS * FDIM);
        #pragma unroll 8
        for (int c = c0; c < c0 + 64; c++) {
            float2 v = __bfloat1622float2(xb[c*64 + f2]);
            s.x += v.x; s.y += v.y;
        }
    }
    sm[p][f2] = s;
    __syncthreads();
    if (p == 0) {
        s = sm[0][f2];
        #pragma unroll
        for (int i = 1; i < 16; i++) { s.x += sm[i][f2].x; s.y += sm[i][f2].y; }
        ((__nv_bfloat162*)MAgg)[b*64 + f2] = __float22bfloat162_rn(s);
    }
}

// ---------------- dense GEMM: UV = A @ Wt^T (+bias on u-half) ----------------
// CTA tile 128x128, K=128 in 4 cp.async stages (K=32 each). 512 thr, 16 warps
// (4m x 4n), warp 32x32. grid (1026, 2). 2 CTAs/SM. smem-staged epilogue.
#define STR2 272
#define SMB2_OFF (128*STR2)
#define GEMM_SMEM (256*STR2)   // 69632

__device__ __forceinline__ void ldmA(uint32_t addr, uint32_t* r){
    asm volatile("ldmatrix.sync.aligned.m8n8.x4.shared.b16 {%0,%1,%2,%3}, [%4];"
        : "=r"(r[0]), "=r"(r[1]), "=r"(r[2]), "=r"(r[3]) : "r"(addr));
}

__global__ void __launch_bounds__(512, 2) gnn_gemm(
    const __nv_bfloat16* __restrict__ X, const float* __restrict__ G, int srcF32,
    const __nv_bfloat16* __restrict__ MAgg,
    const __nv_bfloat16* __restrict__ Wt, const float* __restrict__ bias,
    __nv_bfloat16* __restrict__ UV)
{
    extern __shared__ char smem[];
    uint32_t sb = smem_u32(smem);
    int t = threadIdx.x;
    int wid = t >> 5, lane = t & 31;
    int m0cta = blockIdx.x * 128;
    int nhalf = blockIdx.y;

    int rown = t >> 2;          // 0..127
    int part = t & 3;           // 16B sub-slice within a 64B k-stage
    int row  = m0cta + rown;
    int b    = row / GROWS;
    int node = row - b * GROWS;

    const char* bsrc = (const char*)(Wt + ((size_t)(nhalf*128 + rown))*128);
    uint32_t bdst = sb + SMB2_OFF + rown*STR2;
    uint32_t adst = sb + rown*STR2;

    // ---- 4 cp.async stages (64B of K per stage, 1 CP16/thread/matrix) ----
    #pragma unroll
    for (int s = 0; s < 4; s++) {
        int kb = s*64 + part*16;
        CP16(bdst + kb, bsrc + kb);
        if (node == GROWS - 1) {
            const uint4* src = (const uint4*)((const char*)(MAgg + b*FDIM) + kb);
            *(uint4*)(smem + rown*STR2 + kb) = src[0];
        } else if (!srcF32) {
            const char* src = (const char*)(X + ((size_t)b * XROWS + node) * FDIM) + kb;
            CP16(adst + kb, src);
        } else {
            if (node < CELLS) {
                const float* src = G + ((size_t)b * CELLS + node) * FDIM + (kb >> 1);
                float4 v0 = *(const float4*)(src);
                float4 v1 = *(const float4*)(src + 4);
                uint4 o;
                __nv_bfloat162* ho = (__nv_bfloat162*)&o;
                ho[0] = __float22bfloat162_rn(make_float2(v0.x, v0.y));
                ho[1] = __float22bfloat162_rn(make_float2(v0.z, v0.w));
                ho[2] = __float22bfloat162_rn(make_float2(v1.x, v1.y));
                ho[3] = __float22bfloat162_rn(make_float2(v1.z, v1.w));
                *(uint4*)(smem + rown*STR2 + kb) = o;
            } else {
                uint4 z = make_uint4(0,0,0,0);
                *(uint4*)(smem + rown*STR2 + kb) = z;
            }
        }
        CP_COMMIT();
    }

    int warp_m = wid >> 2;
    int warp_n = wid & 3;
    uint32_t saA = sb + (warp_m*32 + (lane & 15))*STR2 + (lane >> 4)*16;
    uint32_t saB = sb + SMB2_OFF + (warp_n*32 + (lane >> 4)*8 + (lane & 7))*STR2 + ((lane >> 3) & 1)*16;

    float acc[2][4][4];
    #pragma unroll
    for (int i = 0; i < 2; i++)
        #pragma unroll
        for (int j = 0; j < 4; j++)
            #pragma unroll
            for (int q = 0; q < 4; q++) acc[i][j][q] = 0.f;

#define DO_KS(ks) do { \
    uint32_t ko = (ks) * 32; \
    uint32_t a0[4], a1[4], b0[4], b1[4]; \
    ldmA(saA + ko, a0); \
    ldmA(saA + 16*STR2 + ko, a1); \
    ldmA(saB + ko, b0); \
    ldmA(saB + 16*STR2 + ko, b1); \
    uint32_t* afr[2] = { a0, a1 }; \
    uint32_t* bfr[2] = { b0, b1 }; \
    _Pragma("unroll") \
    for (int mf = 0; mf < 2; mf++) \
        _Pragma("unroll") \
        for (int nf = 0; nf < 4; nf++) { \
            uint32_t rb0 = bfr[nf >> 1][(nf & 1)*2]; \
            uint32_t rb1 = bfr[nf >> 1][(nf & 1)*2 + 1]; \
            asm volatile("mma.sync.aligned.m16n8k16.row.col.f32.bf16.bf16.f32 " \
                "{%0,%1,%2,%3}, {%4,%5,%6,%7}, {%8,%9}, {%0,%1,%2,%3};" \
                : "+f"(acc[mf][nf][0]), "+f"(acc[mf][nf][1]), \
                  "+f"(acc[mf][nf][2]), "+f"(acc[mf][nf][3]) \
                : "r"(afr[mf][0]), "r"(afr[mf][1]), "r"(afr[mf][2]), "r"(afr[mf][3]), \
                  "r"(rb0), "r"(rb1)); \
        } \
} while(0)

    CP_WAIT(3); __syncthreads(); DO_KS(0); DO_KS(1);
    CP_WAIT(2); __syncthreads(); DO_KS(2); DO_KS(3);
    CP_WAIT(1); __syncthreads(); DO_KS(4); DO_KS(5);
    CP_WAIT(0); __syncthreads(); DO_KS(6); DO_KS(7);
#undef DO_KS

    // ---- epilogue: stage C tile in A-smem (bf16), then coalesced 16B stores ----
    __syncthreads();   // all ldmatrix reads of A region complete
    int gr = lane >> 2, gc = lane & 3;
    #pragma unroll
    for (int nf = 0; nf < 4; nf++) {
        int coln = warp_n*32 + nf*8 + 2*gc;
        float2 bb = make_float2(0.f, 0.f);
        if (nhalf == 0) bb = *(const float2*)(bias + coln);
        #pragma unroll
        for (int mf = 0; mf < 2; mf++) {
            int r0 = warp_m*32 + mf*16 + gr;
            *(__nv_bfloat162*)(smem + r0*STR2 + coln*2) =
                __float22bfloat162_rn(make_float2(acc[mf][nf][0] + bb.x, acc[mf][nf][1] + bb.y));
            *(__nv_bfloat162*)(smem + (r0 + 8)*STR2 + coln*2) =
                __float22bfloat162_rn(make_float2(acc[mf][nf][2] + bb.x, acc[mf][nf][3] + bb.y));
        }
    }
    __syncthreads();
    #pragma unroll
    for (int it = 0; it < 4; it++) {
        int chunk = it*512 + t;
        int r = chunk >> 4;        // 0..127
        int c16 = chunk & 15;      // 16B chunk within 256B row segment
        uint4 v = *(const uint4*)(smem + r*STR2 + c16*16);
        *(uint4*)((char*)UV + ((size_t)(m0cta + r))*512 + nhalf*256 + c16*16) = v;
    }
}

// ---------------- stencil: y = elu(u + v[meta] + sum v[nbrs]), bf16 adds ----------------
__device__ __forceinline__ void badd8(const __nv_bfloat16* p, __nv_bfloat162* s){
    uint4 v = *(const uint4*)p;
    __nv_bfloat162* h = (__nv_bfloat162*)&v;
    #pragma unroll
    for (int i = 0; i < 4; i++) s[i] = __hadd2(s[i], h[i]);
}

__global__ void gnn_stencil(const __nv_bfloat16* __restrict__ UV, __nv_bfloat16* __restrict__ Y){
    int idx = blockIdx.x * blockDim.x + threadIdx.x;   // BATCH*XROWS*16
    int q = idx & 15;
    int nb = idx >> 4;
    int node = nb % XROWS;
    int b = nb / XROWS;
    const __nv_bfloat16* uvb = UV + (size_t)b * GROWS * 256;
    int qo = q * 8;

    __nv_bfloat162 s[4];
    {
        uint4 v = *(const uint4*)(uvb + (size_t)node*256 + qo);
        __nv_bfloat162* h = (__nv_bfloat162*)&v;
        #pragma unroll
        for (int i = 0; i < 4; i++) s[i] = h[i];
    }
    const __nv_bfloat16* vb = uvb + 128 + qo;
    if (node < CELLS) {
        badd8(vb + (size_t)CELLS*256, s);
        int r = node >> 5, c = node & 31;
        if (r > 0)  badd8(vb + (size_t)(node-32)*256, s);
        if (r < 31) badd8(vb + (size_t)(node+32)*256, s);
        if (c > 0)  badd8(vb + (size_t)(node-1)*256, s);
        if (c < 31) badd8(vb + (size_t)(node+1)*256, s);
    } else {
        badd8(vb + (size_t)(CELLS+1)*256, s);
    }
    uint4 o;
    __nv_bfloat162* ho = (__nv_bfloat162*)&o;
    #pragma unroll
    for (int i = 0; i < 4; i++) {
        float2 f = __bfloat1622float2(s[i]);
        ho[i] = __float22bfloat162_rn(make_float2(elu1(f.x), elu1(f.y)));
    }
    *(uint4*)(Y + ((size_t)b * XROWS + node) * FDIM + qo) = o;
}

// ---------------- gather 5 cells ----------------
__global__ void gather_state(const __nv_bfloat16* __restrict__ X, const int* __restrict__ pos,
                             float* __restrict__ state)
{
    int b = blockIdx.x;
    int f = threadIdx.x;
    int r = pos[2*b + 0];
    int c = pos[2*b + 1];
    const int dr[5] = {-1, 0, 1, 0, 0};
    const int dc[5] = { 0,-1, 0, 1, 0};
    #pragma unroll
    for (int o = 0; o < 5; o++) {
        int j  = (r + dr[o] + 1) * 32 + (c + dc[o] + 1);
        int jr = j / 34, jc = j % 34;
        float v = 0.f;
        if (jr >= 1 && jr <= 32 && jc >= 1 && jc <= 32) {
            int cell = (jr - 1) * 32 + (jc - 1);
            v = __bfloat162float(X[((size_t)b * XROWS + cell) * FDIM + f]);
        }
        state[b * 640 + o * FDIM + f] = v;
    }
}

// ---------------- small MLP GEMM (fp32, f32x2), tile 32x64 ----------------
template<bool ELU>
__global__ void __launch_bounds__(256) mlp_gemm(
    const float* __restrict__ A, const float* __restrict__ W,
    const float* __restrict__ bias, float* __restrict__ C, int K, int N)
{
    __shared__ float sAm[32][36];
    __shared__ float sWm[32][68];
    int t = threadIdx.x;
    int tx = t & 15;
    int ty = t >> 4;
    int m0 = blockIdx.y * 32;
    int n0 = blockIdx.x * 64;

    u64 acc[2][2];
    acc[0][0] = acc[0][1] = acc[1][0] = acc[1][1] = 0ULL;

    int arow = t >> 3, acg = t & 7;
    int wr = t >> 4, wn = (t & 15) * 4;

    for (int kk = 0; kk < K; kk += 32) {
        *(float4*)&sAm[arow][acg*4] = *(const float4*)(A + (size_t)(m0 + arow) * K + kk + acg*4);
        *(float4*)&sWm[wr][wn]      = *(const float4*)(W + (size_t)(kk + wr) * N + n0 + wn);
        *(float4*)&sWm[wr+16][wn]   = *(const float4*)(W + (size_t)(kk + wr + 16) * N + n0 + wn);
        __syncthreads();
        #pragma unroll
        for (int k = 0; k < 32; k++) {
            F2 b0, b1;
            b0.f = *(const float2*)&sWm[k][tx*4];
            b1.f = *(const float2*)&sWm[k][tx*4 + 2];
            #pragma unroll
            for (int i = 0; i < 2; i++) {
                float av = sAm[ty*2+i][k];
                u64 ap = pack2(av, av);
                ffma2(acc[i][0], ap, b0.u);
                ffma2(acc[i][1], ap, b1.u);
            }
        }
        __syncthreads();
    }

    float4 bb = *(const float4*)(bias + n0 + tx*4);
    #pragma unroll
    for (int i = 0; i < 2; i++) {
        F2 u0, u1; u0.u = acc[i][0]; u1.u = acc[i][1];
        float4 o;
        o.x = u0.f.x + bb.x; o.y = u0.f.y + bb.y;
        o.z = u1.f.x + bb.z; o.w = u1.f.y + bb.w;
        if (ELU) { o.x = elu1(o.x); o.y = elu1(o.y); o.z = elu1(o.z); o.w = elu1(o.w); }
        *(float4*)(C + (size_t)(m0 + ty*2 + i) * N + n0 + tx*4) = o;
    }
}

// ---------------- logits + mask ----------------
__global__ void logits_k(const float* __restrict__ P2, const float* __restrict__ W,
                         const float* __restrict__ bias, const int* __restrict__ mask,
                         float* __restrict__ out)
{
    int b = blockIdx.x;
    int a = threadIdx.x;
    if (a >= 19) return;
    float s = bias[a];
    const float* p = P2 + b * 256;
    #pragma unroll 8
    for (int k = 0; k < 256; k++) s += p[k] * W[k * 19 + a];
    int m = mask[b * 19 + a];
    out[b * 19 + a] = s + (m > 0 ? 0.f : -3.4028234663852886e38f);
}

// ---------------- launch ----------------
extern "C" void kernel_launch(void* const* d_in, const int* in_sizes, int n_in,
                              void* d_out, int out_size)
{
    const float* gmap  = (const float*)d_in[0];
    const int*   pos   = (const int*)  d_in[1];
    const int*   amask = (const int*)  d_in[2];
    const float* Ws    = (const float*)d_in[3];
    const float* Wn    = (const float*)d_in[4];
    const float* bs    = (const float*)d_in[5];
    const float* W_d1  = (const float*)d_in[6];
    const float* b_d1  = (const float*)d_in[7];
    const float* W_d2  = (const float*)d_in[8];
    const float* b_d2  = (const float*)d_in[9];
    const float* W_d3  = (const float*)d_in[10];
    const float* b_d3  = (const float*)d_in[11];
    const float* W_p1  = (const float*)d_in[12];
    const float* b_p1  = (const float*)d_in[13];
    const float* W_p2  = (const float*)d_in[14];
    const float* b_p2  = (const float*)d_in[15];
    const float* W_p3  = (const float*)d_in[16];
    const float* b_p3  = (const float*)d_in[17];
    float* out = (float*)d_out;

    __nv_bfloat16 *x0, *x1, *uv, *ma, *wt;
    float *st, *h1, *h2, *ft, *p1, *p2;
    cudaGetSymbolAddress((void**)&x0, g_xb0);
    cudaGetSymbolAddress((void**)&x1, g_xb1);
    cudaGetSymbolAddress((void**)&uv, g_uv);
    cudaGetSymbolAddress((void**)&ma, g_magg);
    cudaGetSymbolAddress((void**)&wt, g_wt);
    cudaGetSymbolAddress((void**)&st, g_state);
    cudaGetSymbolAddress((void**)&h1, g_h1);
    cudaGetSymbolAddress((void**)&h2, g_h2);
    cudaGetSymbolAddress((void**)&ft, g_ft);
    cudaGetSymbolAddress((void**)&p1, g_p1);
    cudaGetSymbolAddress((void**)&p2, g_p2);

    cudaFuncSetAttribute(gnn_gemm, cudaFuncAttributeMaxDynamicSharedMemorySize, GEMM_SMEM);

    prep_wt<<<(3*256*128)/256, 256>>>(Ws, Wn, wt);

    dim3 gg(MTOT/128, 2);
    // layer 0 (A from gmap fp32)
    meta_agg<<<BATCH, 1024>>>(nullptr, gmap, 1, ma);
    gnn_gemm<<<gg, 512, GEMM_SMEM>>>(nullptr, gmap, 1, ma, wt, bs, uv);
    gnn_stencil<<<(BATCH*XROWS*16)/256, 256>>>(uv, x0);
    // layer 1
    meta_agg<<<BATCH, 1024>>>(x0, nullptr, 0, ma);
    gnn_gemm<<<gg, 512, GEMM_SMEM>>>(x0, nullptr, 0, ma, wt + 256*128, bs + 128, uv);
    gnn_stencil<<<(BATCH*XROWS*16)/256, 256>>>(uv, x1);
    // layer 2
    meta_agg<<<BATCH, 1024>>>(x1, nullptr, 0, ma);
    gnn_gemm<<<gg, 512, GEMM_SMEM>>>(x1, nullptr, 0, ma, wt + 2*256*128, bs + 256, uv);
    gnn_stencil<<<(BATCH*XROWS*16)/256, 256>>>(uv, x0);

    gather_state<<<BATCH, 128>>>(x0, pos, st);

    mlp_gemm<true><<<dim3(8, 4), 256>>>(st, W_d1, b_d1, h1, 640, 512);
    mlp_gemm<true><<<dim3(8, 4), 256>>>(h1, W_d2, b_d2, h2, 512, 512);
    mlp_gemm<true><<<dim3(4, 4), 256>>>(h2, W_d3, b_d3, ft, 512, 256);
    mlp_gemm<true><<<dim3(4, 4), 256>>>(ft, W_p1, b_p1, p1, 256, 256);
    mlp_gemm<true><<<dim3(4, 4), 256>>>(p1, W_p2, b_p2, p2, 256, 256);

    logits_k<<<BATCH, 32>>>(p2, W_p3, b_p3, amask, out);
}